// round 1
// baseline (speedup 1.0000x reference)
#include <cuda_runtime.h>
#include <cstdint>

#define NN 100000
#define NE 1600000
#define D  128

// Scratch: Z = feature @ W^T  (51.2 MB) — device global, no allocation.
__device__ float g_Z[(size_t)NN * D];
__device__ int   g_is64;

// ---------------------------------------------------------------------------
// Detect index dtype: int64 values < 2^31 have all-zero high words.
// For int32 random values in [0,100000), P(1024 consecutive odd words all 0)≈0.
// ---------------------------------------------------------------------------
__global__ void detect_idx_kernel(const unsigned int* __restrict__ w) {
    __shared__ int any;
    if (threadIdx.x == 0) any = 0;
    __syncthreads();
    int nz = 0;
    for (int i = threadIdx.x; i < 1024; i += blockDim.x)
        nz |= (w[2 * i + 1] != 0u);
    if (nz) atomicOr(&any, 1);
    __syncthreads();
    if (threadIdx.x == 0) g_is64 = (any == 0) ? 1 : 0;
}

// ---------------------------------------------------------------------------
// out[n][o] = b[o]  (out is poisoned before timing; also fuses the bias)
// ---------------------------------------------------------------------------
__global__ void init_out_kernel(float4* __restrict__ out, const float4* __restrict__ b) {
    int i = blockIdx.x * blockDim.x + threadIdx.x;   // < NN*D/4 = 3.2M
    out[i] = b[i & 31];                              // 32 float4 per row
}

// ---------------------------------------------------------------------------
// Z = X @ W^T, fp32. Block tile 32 rows x 128 cols, thread tile 4x4.
// Shared: Wt[128][132] (W transposed, padded) + Ft[128][36] (X transposed).
// Inner loop per d: broadcast LDS.128 (4 rows) + LDS.128 (4 cols) + 16 FFMA.
// ---------------------------------------------------------------------------
#define WT_STRIDE 132
#define FT_STRIDE 36
#define GEMM_SMEM ((128 * WT_STRIDE + 128 * FT_STRIDE) * 4)

__global__ void __launch_bounds__(256, 2)
gemm_kernel(const float* __restrict__ X, const float* __restrict__ W) {
    extern __shared__ float sm[];
    float* Wt = sm;                       // [128][WT_STRIDE]
    float* Ft = sm + 128 * WT_STRIDE;     // [128][FT_STRIDE]
    const int tid  = threadIdx.x;
    const int row0 = blockIdx.x * 32;

    // Load W [128x128] transposed into shared: Wt[d][c] = W[c][d]
#pragma unroll
    for (int i = 0; i < 64; i++) {
        int idx = i * 256 + tid;          // = c*128 + d, coalesced over d
        int c = idx >> 7, d = idx & 127;
        Wt[d * WT_STRIDE + c] = W[idx];
    }
    // Load 32 feature rows transposed: Ft[d][r] = X[row0+r][d]
#pragma unroll
    for (int i = 0; i < 16; i++) {
        int idx = i * 256 + tid;
        int r = idx >> 7, d = idx & 127;
        Ft[d * FT_STRIDE + r] = X[(size_t)(row0 + r) * D + d];
    }
    __syncthreads();

    const int warp = tid >> 5, lane = tid & 31;
    const int r0 = warp * 4;              // 8 warps x 4 rows = 32 rows
    const int c0 = lane * 4;              // 32 lanes x 4 cols = 128 cols

    float acc[4][4] = {};
#pragma unroll 4
    for (int d = 0; d < 128; d++) {
        float4 f = *(const float4*)&Ft[d * FT_STRIDE + r0];   // warp broadcast
        float4 w = *(const float4*)&Wt[d * WT_STRIDE + c0];
        acc[0][0] += f.x * w.x; acc[0][1] += f.x * w.y; acc[0][2] += f.x * w.z; acc[0][3] += f.x * w.w;
        acc[1][0] += f.y * w.x; acc[1][1] += f.y * w.y; acc[1][2] += f.y * w.z; acc[1][3] += f.y * w.w;
        acc[2][0] += f.z * w.x; acc[2][1] += f.z * w.y; acc[2][2] += f.z * w.z; acc[2][3] += f.z * w.w;
        acc[3][0] += f.w * w.x; acc[3][1] += f.w * w.y; acc[3][2] += f.w * w.z; acc[3][3] += f.w * w.w;
    }

#pragma unroll
    for (int i = 0; i < 4; i++) {
        float4 v = make_float4(acc[i][0], acc[i][1], acc[i][2], acc[i][3]);
        *(float4*)&g_Z[(size_t)(row0 + r0 + i) * D + c0] = v;
    }
}

// ---------------------------------------------------------------------------
// out[dst] += Z[src], one warp per edge, 4 edges per warp.
// Each lane handles a float4 column chunk; vectorized red.global.add.v4.f32
// quarters the L2 atomic op count vs scalar atomicAdd.
// ---------------------------------------------------------------------------
__global__ void __launch_bounds__(256)
scatter_kernel(const void* __restrict__ srcp, const void* __restrict__ dstp,
               float* __restrict__ out) {
    const int gwarp = (blockIdx.x * blockDim.x + threadIdx.x) >> 5;
    const int lane  = threadIdx.x & 31;
    const int is64  = g_is64;
    const int e0 = gwarp * 4;

#pragma unroll
    for (int k = 0; k < 4; k++) {
        const int e = e0 + k;
        int s, t;
        if (is64) {
            s = (int)((const long long*)srcp)[e];
            t = (int)((const long long*)dstp)[e];
        } else {
            s = ((const int*)srcp)[e];
            t = ((const int*)dstp)[e];
        }
        float4 v = *(const float4*)(g_Z + (size_t)s * D + lane * 4);
        float* op = out + (size_t)t * D + lane * 4;
        asm volatile("red.global.add.v4.f32 [%0], {%1,%2,%3,%4};"
                     :: "l"(op), "f"(v.x), "f"(v.y), "f"(v.z), "f"(v.w)
                     : "memory");
    }
}

// ---------------------------------------------------------------------------
extern "C" void kernel_launch(void* const* d_in, const int* in_sizes, int n_in,
                              void* d_out, int out_size) {
    const float* feature = (const float*)d_in[0];
    const void*  src     = d_in[1];
    const void*  dst     = d_in[2];
    const float* W       = (const float*)d_in[3];
    const float* b       = (const float*)d_in[4];
    float*       out     = (float*)d_out;

    cudaFuncSetAttribute(gemm_kernel,
                         cudaFuncAttributeMaxDynamicSharedMemorySize, GEMM_SMEM);

    detect_idx_kernel<<<1, 256>>>((const unsigned int*)src);
    init_out_kernel<<<(NN * D / 4) / 256, 256>>>((float4*)d_out, (const float4*)b);
    gemm_kernel<<<NN / 32, 256, GEMM_SMEM>>>(feature, W);
    scatter_kernel<<<NE / 32, 256>>>(src, dst, out);
}

// round 2
// speedup vs baseline: 1.2799x; 1.2799x over previous
#include <cuda_runtime.h>
#include <cstdint>

#define NN 100000
#define NE 1600000
#define D  128

#define SCAN_B 256
#define NBLK ((NN + SCAN_B - 1) / SCAN_B)   // 391

// Device-global scratch (no allocations allowed)
__device__ float g_Z[(size_t)NN * D];       // feature @ W^T   (51.2 MB)
__device__ int   g_esrc[NE];                // CSR: src per slot (6.4 MB)
__device__ int   g_cnt[NN];                 // degree histogram
__device__ int   g_off[NN];                 // CSR row offsets (exclusive scan)
__device__ int   g_cur[NN];                 // fill cursors
__device__ int   g_bsum[NBLK];              // scan block sums
__device__ int   g_is64;

// ---------------------------------------------------------------------------
// Index dtype detection: int64 values < 2^31 have all-zero high words.
// ---------------------------------------------------------------------------
__global__ void detect_idx_kernel(const unsigned int* __restrict__ w) {
    __shared__ int any;
    if (threadIdx.x == 0) any = 0;
    __syncthreads();
    int nz = 0;
    for (int i = threadIdx.x; i < 1024; i += blockDim.x)
        nz |= (w[2 * i + 1] != 0u);
    if (nz) atomicOr(&any, 1);
    __syncthreads();
    if (threadIdx.x == 0) g_is64 = (any == 0) ? 1 : 0;
}

__device__ __forceinline__ int load_idx(const void* p, int e, int is64) {
    return is64 ? (int)((const long long*)p)[e] : ((const int*)p)[e];
}

// ---------------------------------------------------------------------------
// CSR build: zero -> histogram(dst) -> 3-phase exclusive scan -> fill(src)
// ---------------------------------------------------------------------------
__global__ void zero_cnt_kernel() {
    int i = blockIdx.x * blockDim.x + threadIdx.x;
    if (i < NN) g_cnt[i] = 0;
}

__global__ void hist_kernel(const void* __restrict__ dstp) {
    int e = blockIdx.x * blockDim.x + threadIdx.x;
    if (e >= NE) return;
    atomicAdd(&g_cnt[load_idx(dstp, e, g_is64)], 1);   // REDG, spread addrs
}

__global__ void scan_a_kernel() {                       // per-block exclusive scan
    __shared__ int s[SCAN_B];
    int tid = threadIdx.x;
    int i = blockIdx.x * SCAN_B + tid;
    int v = (i < NN) ? g_cnt[i] : 0;
    s[tid] = v;
    __syncthreads();
#pragma unroll
    for (int o = 1; o < SCAN_B; o <<= 1) {
        int t = (tid >= o) ? s[tid - o] : 0;
        __syncthreads();
        s[tid] += t;
        __syncthreads();
    }
    if (i < NN) g_off[i] = s[tid] - v;                  // exclusive
    if (tid == SCAN_B - 1) g_bsum[blockIdx.x] = s[tid]; // block total
}

__global__ void scan_b_kernel() {                       // scan the 391 block sums
    __shared__ int s[512];
    int tid = threadIdx.x;
    int v = (tid < NBLK) ? g_bsum[tid] : 0;
    s[tid] = v;
    __syncthreads();
#pragma unroll
    for (int o = 1; o < 512; o <<= 1) {
        int t = (tid >= o) ? s[tid - o] : 0;
        __syncthreads();
        s[tid] += t;
        __syncthreads();
    }
    if (tid < NBLK) g_bsum[tid] = s[tid] - v;           // exclusive
}

__global__ void scan_c_kernel() {                       // add block prefix, seed cursors
    int i = blockIdx.x * blockDim.x + threadIdx.x;
    if (i >= NN) return;
    int o = g_off[i] + g_bsum[i / SCAN_B];
    g_off[i] = o;
    g_cur[i] = o;
}

__global__ void fill_kernel(const void* __restrict__ srcp,
                            const void* __restrict__ dstp) {
    int e = blockIdx.x * blockDim.x + threadIdx.x;
    if (e >= NE) return;
    int is64 = g_is64;
    int s = load_idx(srcp, e, is64);
    int d = load_idx(dstp, e, is64);
    int pos = atomicAdd(&g_cur[d], 1);
    g_esrc[pos] = s;
}

// ---------------------------------------------------------------------------
// Z = X @ W^T, fp32. Block tile 32x128, thread tile 4x4 (near fp32 peak).
// ---------------------------------------------------------------------------
#define WT_STRIDE 132
#define FT_STRIDE 36
#define GEMM_SMEM ((128 * WT_STRIDE + 128 * FT_STRIDE) * 4)

__global__ void __launch_bounds__(256, 2)
gemm_kernel(const float* __restrict__ X, const float* __restrict__ W) {
    extern __shared__ float sm[];
    float* Wt = sm;                       // [128][WT_STRIDE]
    float* Ft = sm + 128 * WT_STRIDE;     // [128][FT_STRIDE]
    const int tid  = threadIdx.x;
    const int row0 = blockIdx.x * 32;

#pragma unroll
    for (int i = 0; i < 64; i++) {
        int idx = i * 256 + tid;          // = c*128 + d
        int c = idx >> 7, d = idx & 127;
        Wt[d * WT_STRIDE + c] = W[idx];
    }
#pragma unroll
    for (int i = 0; i < 16; i++) {
        int idx = i * 256 + tid;
        int r = idx >> 7, d = idx & 127;
        Ft[d * FT_STRIDE + r] = X[(size_t)(row0 + r) * D + d];
    }
    __syncthreads();

    const int warp = tid >> 5, lane = tid & 31;
    const int r0 = warp * 4;
    const int c0 = lane * 4;

    float acc[4][4] = {};
#pragma unroll 4
    for (int d = 0; d < 128; d++) {
        float4 f = *(const float4*)&Ft[d * FT_STRIDE + r0];
        float4 w = *(const float4*)&Wt[d * WT_STRIDE + c0];
        acc[0][0] += f.x * w.x; acc[0][1] += f.x * w.y; acc[0][2] += f.x * w.z; acc[0][3] += f.x * w.w;
        acc[1][0] += f.y * w.x; acc[1][1] += f.y * w.y; acc[1][2] += f.y * w.z; acc[1][3] += f.y * w.w;
        acc[2][0] += f.z * w.x; acc[2][1] += f.z * w.y; acc[2][2] += f.z * w.z; acc[2][3] += f.z * w.w;
        acc[3][0] += f.w * w.x; acc[3][1] += f.w * w.y; acc[3][2] += f.w * w.z; acc[3][3] += f.w * w.w;
    }

#pragma unroll
    for (int i = 0; i < 4; i++) {
        float4 v = make_float4(acc[i][0], acc[i][1], acc[i][2], acc[i][3]);
        *(float4*)&g_Z[(size_t)(row0 + r0 + i) * D + c0] = v;
    }
}

// ---------------------------------------------------------------------------
// Pull-mode aggregation: one warp per node, lane = float4 column chunk.
// out[n] = b + sum_{e in CSR row n} Z[src[e]].  No atomics, single write.
// ---------------------------------------------------------------------------
__global__ void __launch_bounds__(256)
gather_kernel(const float4* __restrict__ b, float* __restrict__ out) {
    const int node = (blockIdx.x * blockDim.x + threadIdx.x) >> 5;
    if (node >= NN) return;
    const int lane = threadIdx.x & 31;

    const int beg = g_off[node];
    const int end = beg + g_cnt[node];

    float4 acc = b[lane];                 // bias fused; L1-broadcast

    int e = beg;
    // 2-wide unroll for MLP
    for (; e + 2 <= end; e += 2) {
        int s0 = g_esrc[e];
        int s1 = g_esrc[e + 1];
        float4 v0 = *(const float4*)(g_Z + (size_t)s0 * D + lane * 4);
        float4 v1 = *(const float4*)(g_Z + (size_t)s1 * D + lane * 4);
        acc.x += v0.x; acc.y += v0.y; acc.z += v0.z; acc.w += v0.w;
        acc.x += v1.x; acc.y += v1.y; acc.z += v1.z; acc.w += v1.w;
    }
    if (e < end) {
        int s0 = g_esrc[e];
        float4 v0 = *(const float4*)(g_Z + (size_t)s0 * D + lane * 4);
        acc.x += v0.x; acc.y += v0.y; acc.z += v0.z; acc.w += v0.w;
    }

    *(float4*)(out + (size_t)node * D + lane * 4) = acc;
}

// ---------------------------------------------------------------------------
extern "C" void kernel_launch(void* const* d_in, const int* in_sizes, int n_in,
                              void* d_out, int out_size) {
    const float* feature = (const float*)d_in[0];
    const void*  src     = d_in[1];
    const void*  dst     = d_in[2];
    const float* W       = (const float*)d_in[3];
    const float* b       = (const float*)d_in[4];
    float*       out     = (float*)d_out;

    cudaFuncSetAttribute(gemm_kernel,
                         cudaFuncAttributeMaxDynamicSharedMemorySize, GEMM_SMEM);

    detect_idx_kernel<<<1, 256>>>((const unsigned int*)src);
    zero_cnt_kernel<<<NBLK, SCAN_B>>>();
    hist_kernel<<<(NE + 255) / 256, 256>>>(dst);
    scan_a_kernel<<<NBLK, SCAN_B>>>();
    scan_b_kernel<<<1, 512>>>();
    scan_c_kernel<<<NBLK, SCAN_B>>>();
    fill_kernel<<<(NE + 255) / 256, 256>>>(src, dst);
    gemm_kernel<<<NN / 32, 256, GEMM_SMEM>>>(feature, W);
    gather_kernel<<<(NN * 32 + 255) / 256, 256>>>((const float4*)b, out);
}

// round 3
// speedup vs baseline: 1.8276x; 1.4280x over previous
#include <cuda_runtime.h>
#include <cstdint>

#define NN 100000
#define NE 1600000
#define D  128

#define SCAN_B 256
#define NBLK ((NN + SCAN_B - 1) / SCAN_B)   // 391
#define GEMM_BLOCKS ((NN + 127) / 128)      // 782

// Device-global scratch (no allocations allowed)
__device__ float g_Z[(size_t)NN * D];       // feature @ W^T   (51.2 MB)
__device__ int   g_esrc[NE];                // CSR: src per slot
__device__ int   g_cnt[NN];
__device__ int   g_off[NN];
__device__ int   g_cur[NN];
__device__ int   g_bsum[NBLK];
__device__ int   g_is64;

// ---------------------------------------------------------------------------
// detect idx dtype (int64 high words all zero) + zero histogram, one kernel
// ---------------------------------------------------------------------------
__global__ void prep_kernel(const unsigned int* __restrict__ w) {
    int i = blockIdx.x * blockDim.x + threadIdx.x;
    if (i < NN) g_cnt[i] = 0;
    if (blockIdx.x == 0) {
        __shared__ int any;
        if (threadIdx.x == 0) any = 0;
        __syncthreads();
        int nz = 0;
        for (int j = threadIdx.x; j < 1024; j += blockDim.x)
            nz |= (w[2 * j + 1] != 0u);
        if (nz) atomicOr(&any, 1);
        __syncthreads();
        if (threadIdx.x == 0) g_is64 = (any == 0) ? 1 : 0;
    }
}

__device__ __forceinline__ int load_idx(const void* p, int e, int is64) {
    return is64 ? (int)((const long long*)p)[e] : ((const int*)p)[e];
}

// ---------------------------------------------------------------------------
// CSR build: histogram(dst) -> 3-phase exclusive scan -> fill(src)
// ---------------------------------------------------------------------------
__global__ void hist_kernel(const void* __restrict__ dstp) {
    int e = blockIdx.x * blockDim.x + threadIdx.x;
    if (e >= NE) return;
    atomicAdd(&g_cnt[load_idx(dstp, e, g_is64)], 1);
}

__global__ void scan_a_kernel() {
    __shared__ int s[SCAN_B];
    int tid = threadIdx.x;
    int i = blockIdx.x * SCAN_B + tid;
    int v = (i < NN) ? g_cnt[i] : 0;
    s[tid] = v;
    __syncthreads();
#pragma unroll
    for (int o = 1; o < SCAN_B; o <<= 1) {
        int t = (tid >= o) ? s[tid - o] : 0;
        __syncthreads();
        s[tid] += t;
        __syncthreads();
    }
    if (i < NN) g_off[i] = s[tid] - v;
    if (tid == SCAN_B - 1) g_bsum[blockIdx.x] = s[tid];
}

__global__ void scan_b_kernel() {
    __shared__ int s[512];
    int tid = threadIdx.x;
    int v = (tid < NBLK) ? g_bsum[tid] : 0;
    s[tid] = v;
    __syncthreads();
#pragma unroll
    for (int o = 1; o < 512; o <<= 1) {
        int t = (tid >= o) ? s[tid - o] : 0;
        __syncthreads();
        s[tid] += t;
        __syncthreads();
    }
    if (tid < NBLK) g_bsum[tid] = s[tid] - v;
}

__global__ void scan_c_kernel() {
    int i = blockIdx.x * blockDim.x + threadIdx.x;
    if (i >= NN) return;
    int o = g_off[i] + g_bsum[i / SCAN_B];
    g_off[i] = o;
    g_cur[i] = o;
}

__global__ void fill_kernel(const void* __restrict__ srcp,
                            const void* __restrict__ dstp) {
    int e = blockIdx.x * blockDim.x + threadIdx.x;
    if (e >= NE) return;
    int is64 = g_is64;
    int s = load_idx(srcp, e, is64);
    int d = load_idx(dstp, e, is64);
    int pos = atomicAdd(&g_cur[d], 1);
    g_esrc[pos] = s;
}

// ---------------------------------------------------------------------------
// Tensor-core GEMM: Z = X @ W^T in bf16-split (hi*hi + hi*lo + lo*hi).
// Block: 128 rows x 128 cols, 8 warps (warp tile 32x64 = 2 m16 x 8 n8).
// Operands staged in smem IN FRAGMENT LAYOUT (16B per lane -> conflict-free).
// ---------------------------------------------------------------------------
#define TC_SMEM (128 * 1024)

// cvt.rn.bf16x2.f32 d, a, b : d.high = bf16(a), d.low = bf16(b)
__device__ __forceinline__ void bf16_split2(float x, float y,
                                            uint32_t& hi, uint32_t& lo) {
    asm("cvt.rn.bf16x2.f32 %0, %1, %2;" : "=r"(hi) : "f"(y), "f"(x));
    float xh = __uint_as_float(hi << 16);
    float yh = __uint_as_float(hi & 0xffff0000u);
    asm("cvt.rn.bf16x2.f32 %0, %1, %2;" : "=r"(lo) : "f"(y - yh), "f"(x - xh));
}

__device__ __forceinline__ void mma16816(float* c, const uint4& a,
                                         uint32_t b0, uint32_t b1) {
    asm volatile(
        "mma.sync.aligned.m16n8k16.row.col.f32.bf16.bf16.f32 "
        "{%0,%1,%2,%3}, {%4,%5,%6,%7}, {%8,%9}, {%0,%1,%2,%3};"
        : "+f"(c[0]), "+f"(c[1]), "+f"(c[2]), "+f"(c[3])
        : "r"(a.x), "r"(a.y), "r"(a.z), "r"(a.w), "r"(b0), "r"(b1));
}

__global__ void __launch_bounds__(256, 1)
tc_gemm_kernel(const float* __restrict__ X, const float* __restrict__ W) {
    extern __shared__ uint4 sm[];
    uint4* Ahi = sm;           // [ (ks*8+mt)*32 + lane ]  : a0..a3 hi  (32KB)
    uint4* Alo = sm + 2048;    // same layout, lo                        (32KB)
    uint4* Bsm = sm + 4096;    // [ (ks*16+nt)*32 + lane ]: b0hi,b1hi,b0lo,b1lo (64KB)

    const int tid  = threadIdx.x;
    const int bRow = blockIdx.x * 128;

    // ---- stage W fragments: 8 ks x 16 nt x 32 lanes = 4096 entries ----
#pragma unroll
    for (int i = 0; i < 16; i++) {
        int e = i * 256 + tid;
        int lane = e & 31, rest = e >> 5;
        int nt = rest & 15, ks = rest >> 4;
        int g = lane >> 2, t4 = lane & 3;
        int n = nt * 8 + g, k = ks * 16 + t4 * 2;
        float2 p0 = *(const float2*)&W[n * D + k];
        float2 p1 = *(const float2*)&W[n * D + k + 8];
        uint4 v;
        uint32_t h0, l0, h1, l1;
        bf16_split2(p0.x, p0.y, h0, l0);
        bf16_split2(p1.x, p1.y, h1, l1);
        v.x = h0; v.y = h1; v.z = l0; v.w = l1;
        Bsm[(ks * 16 + nt) * 32 + lane] = v;
    }

    // ---- stage X fragments: 8 ks x 8 mt x 32 lanes = 2048 entries ----
#pragma unroll
    for (int i = 0; i < 8; i++) {
        int e = i * 256 + tid;
        int lane = e & 31, rest = e >> 5;
        int mt = rest & 7, ks = rest >> 3;
        int g = lane >> 2, t4 = lane & 3;
        int r1 = bRow + mt * 16 + g;
        int r2 = r1 + 8;
        int k  = ks * 16 + t4 * 2;
        int r1c = (r1 < NN) ? r1 : NN - 1;   // clamp: values unused
        int r2c = (r2 < NN) ? r2 : NN - 1;
        float2 p0 = *(const float2*)&X[(size_t)r1c * D + k];
        float2 p1 = *(const float2*)&X[(size_t)r2c * D + k];
        float2 p2 = *(const float2*)&X[(size_t)r1c * D + k + 8];
        float2 p3 = *(const float2*)&X[(size_t)r2c * D + k + 8];
        uint4 vh, vl;
        bf16_split2(p0.x, p0.y, vh.x, vl.x);
        bf16_split2(p1.x, p1.y, vh.y, vl.y);
        bf16_split2(p2.x, p2.y, vh.z, vl.z);
        bf16_split2(p3.x, p3.y, vh.w, vl.w);
        int idx = (ks * 8 + mt) * 32 + lane;
        Ahi[idx] = vh;
        Alo[idx] = vl;
    }
    __syncthreads();

    // ---- main loop ----
    const int warp = tid >> 5, lane = tid & 31;
    const int rg = warp >> 1, cg = warp & 1;   // 4 row groups x 2 col groups
    const int g = lane >> 2, t4 = lane & 3;

    float acc[2][8][4];
#pragma unroll
    for (int m = 0; m < 2; m++)
#pragma unroll
        for (int n = 0; n < 8; n++)
#pragma unroll
            for (int q = 0; q < 4; q++) acc[m][n][q] = 0.f;

#pragma unroll
    for (int ks = 0; ks < 8; ks++) {
        uint4 ah[2], al[2];
#pragma unroll
        for (int m = 0; m < 2; m++) {
            int idx = (ks * 8 + rg * 2 + m) * 32 + lane;
            ah[m] = Ahi[idx];
            al[m] = Alo[idx];
        }
#pragma unroll
        for (int n = 0; n < 8; n++) {
            uint4 b = Bsm[(ks * 16 + cg * 8 + n) * 32 + lane];
#pragma unroll
            for (int m = 0; m < 2; m++) {
                mma16816(acc[m][n], ah[m], b.x, b.y);   // hi*hi
                mma16816(acc[m][n], ah[m], b.z, b.w);   // hi*lo
                mma16816(acc[m][n], al[m], b.x, b.y);   // lo*hi
            }
        }
    }

    // ---- epilogue: write Z ----
#pragma unroll
    for (int m = 0; m < 2; m++) {
        int row = bRow + (rg * 2 + m) * 16 + g;
#pragma unroll
        for (int n = 0; n < 8; n++) {
            int col = cg * 64 + n * 8 + t4 * 2;
            if (row < NN)
                *(float2*)&g_Z[(size_t)row * D + col] =
                    make_float2(acc[m][n][0], acc[m][n][1]);
            if (row + 8 < NN)
                *(float2*)&g_Z[(size_t)(row + 8) * D + col] =
                    make_float2(acc[m][n][2], acc[m][n][3]);
        }
    }
}

// ---------------------------------------------------------------------------
// Pull-mode aggregation: one warp per node, lane = float4 column chunk.
// ---------------------------------------------------------------------------
__global__ void __launch_bounds__(256)
gather_kernel(const float4* __restrict__ b, float* __restrict__ out) {
    const int node = (blockIdx.x * blockDim.x + threadIdx.x) >> 5;
    if (node >= NN) return;
    const int lane = threadIdx.x & 31;

    const int beg = g_off[node];
    const int end = beg + g_cnt[node];

    float4 acc = b[lane];

    int e = beg;
    for (; e + 2 <= end; e += 2) {
        int s0 = g_esrc[e];
        int s1 = g_esrc[e + 1];
        float4 v0 = *(const float4*)(g_Z + (size_t)s0 * D + lane * 4);
        float4 v1 = *(const float4*)(g_Z + (size_t)s1 * D + lane * 4);
        acc.x += v0.x; acc.y += v0.y; acc.z += v0.z; acc.w += v0.w;
        acc.x += v1.x; acc.y += v1.y; acc.z += v1.z; acc.w += v1.w;
    }
    if (e < end) {
        int s0 = g_esrc[e];
        float4 v0 = *(const float4*)(g_Z + (size_t)s0 * D + lane * 4);
        acc.x += v0.x; acc.y += v0.y; acc.z += v0.z; acc.w += v0.w;
    }

    *(float4*)(out + (size_t)node * D + lane * 4) = acc;
}

// ---------------------------------------------------------------------------
extern "C" void kernel_launch(void* const* d_in, const int* in_sizes, int n_in,
                              void* d_out, int out_size) {
    const float* feature = (const float*)d_in[0];
    const void*  src     = d_in[1];
    const void*  dst     = d_in[2];
    const float* W       = (const float*)d_in[3];
    const float* b       = (const float*)d_in[4];
    float*       out     = (float*)d_out;

    cudaFuncSetAttribute(tc_gemm_kernel,
                         cudaFuncAttributeMaxDynamicSharedMemorySize, TC_SMEM);

    prep_kernel<<<NBLK, SCAN_B>>>((const unsigned int*)src);
    hist_kernel<<<(NE + 255) / 256, 256>>>(dst);
    scan_a_kernel<<<NBLK, SCAN_B>>>();
    scan_b_kernel<<<1, 512>>>();
    scan_c_kernel<<<NBLK, SCAN_B>>>();
    fill_kernel<<<(NE + 255) / 256, 256>>>(src, dst);
    tc_gemm_kernel<<<GEMM_BLOCKS, 256, TC_SMEM>>>(feature, W);
    gather_kernel<<<(NN * 32 + 255) / 256, 256>>>((const float4*)b, out);
}

// round 4
// speedup vs baseline: 1.9934x; 1.0907x over previous
#include <cuda_runtime.h>
#include <cuda_fp16.h>
#include <cstdint>

#define NN 100000
#define NE 1600000
#define D  128

#define SCAN_B 256
#define NBLK ((NN + SCAN_B - 1) / SCAN_B)   // 391
#define GEMM_BLOCKS ((NN + 127) / 128)      // 782

// Device-global scratch (no allocations allowed)
__device__ __half g_Zh[(size_t)NN * D];     // feature @ W^T in fp16 (25.6 MB)
__device__ int    g_esrc[NE];               // CSR: src per slot
__device__ int    g_cnt[NN];
__device__ int    g_off[NN];
__device__ int    g_cur[NN];
__device__ int    g_bsum[NBLK];
__device__ int    g_is64;

// ---------------------------------------------------------------------------
// detect idx dtype (int64 high words all zero) + zero histogram, one kernel
// ---------------------------------------------------------------------------
__global__ void prep_kernel(const unsigned int* __restrict__ w) {
    int i = blockIdx.x * blockDim.x + threadIdx.x;
    if (i < NN) g_cnt[i] = 0;
    if (blockIdx.x == 0) {
        __shared__ int any;
        if (threadIdx.x == 0) any = 0;
        __syncthreads();
        int nz = 0;
        for (int j = threadIdx.x; j < 1024; j += blockDim.x)
            nz |= (w[2 * j + 1] != 0u);
        if (nz) atomicOr(&any, 1);
        __syncthreads();
        if (threadIdx.x == 0) g_is64 = (any == 0) ? 1 : 0;
    }
}

__device__ __forceinline__ int load_idx(const void* p, int e, int is64) {
    return is64 ? (int)((const long long*)p)[e] : ((const int*)p)[e];
}

// ---------------------------------------------------------------------------
// CSR build: histogram(dst) -> scan (2 kernels) -> fill(src)
// ---------------------------------------------------------------------------
__global__ void hist_kernel(const void* __restrict__ dstp) {
    int e = blockIdx.x * blockDim.x + threadIdx.x;
    if (e >= NE) return;
    atomicAdd(&g_cnt[load_idx(dstp, e, g_is64)], 1);
}

__global__ void scan_a_kernel() {                 // per-block exclusive scan
    __shared__ int s[SCAN_B];
    int tid = threadIdx.x;
    int i = blockIdx.x * SCAN_B + tid;
    int v = (i < NN) ? g_cnt[i] : 0;
    s[tid] = v;
    __syncthreads();
#pragma unroll
    for (int o = 1; o < SCAN_B; o <<= 1) {
        int t = (tid >= o) ? s[tid - o] : 0;
        __syncthreads();
        s[tid] += t;
        __syncthreads();
    }
    if (i < NN) g_off[i] = s[tid] - v;
    if (tid == SCAN_B - 1) g_bsum[blockIdx.x] = s[tid];
}

// Adds this block's global prefix (reduced inline from g_bsum) + seeds cursors.
__global__ void scan_c_kernel() {
    __shared__ int s[SCAN_B];
    int tid = threadIdx.x;
    int partial = 0;
    for (int j = tid; j < blockIdx.x; j += SCAN_B) partial += g_bsum[j];
    s[tid] = partial;
    __syncthreads();
#pragma unroll
    for (int o = SCAN_B / 2; o > 0; o >>= 1) {
        if (tid < o) s[tid] += s[tid + o];
        __syncthreads();
    }
    int pre = s[0];
    int i = blockIdx.x * SCAN_B + tid;
    if (i < NN) {
        int o = g_off[i] + pre;
        g_off[i] = o;
        g_cur[i] = o;
    }
}

__global__ void fill_kernel(const void* __restrict__ srcp,
                            const void* __restrict__ dstp) {
    int e = blockIdx.x * blockDim.x + threadIdx.x;
    if (e >= NE) return;
    int is64 = g_is64;
    int s = load_idx(srcp, e, is64);
    int d = load_idx(dstp, e, is64);
    int pos = atomicAdd(&g_cur[d], 1);
    g_esrc[pos] = s;
}

// ---------------------------------------------------------------------------
// Tensor-core GEMM: Z = X @ W^T in bf16-split (hi*hi + hi*lo + lo*hi).
// Output written as fp16 (halves downstream gather traffic).
// ---------------------------------------------------------------------------
#define TC_SMEM (128 * 1024)

__device__ __forceinline__ void bf16_split2(float x, float y,
                                            uint32_t& hi, uint32_t& lo) {
    asm("cvt.rn.bf16x2.f32 %0, %1, %2;" : "=r"(hi) : "f"(y), "f"(x));
    float xh = __uint_as_float(hi << 16);
    float yh = __uint_as_float(hi & 0xffff0000u);
    asm("cvt.rn.bf16x2.f32 %0, %1, %2;" : "=r"(lo) : "f"(y - yh), "f"(x - xh));
}

__device__ __forceinline__ void mma16816(float* c, const uint4& a,
                                         uint32_t b0, uint32_t b1) {
    asm volatile(
        "mma.sync.aligned.m16n8k16.row.col.f32.bf16.bf16.f32 "
        "{%0,%1,%2,%3}, {%4,%5,%6,%7}, {%8,%9}, {%0,%1,%2,%3};"
        : "+f"(c[0]), "+f"(c[1]), "+f"(c[2]), "+f"(c[3])
        : "r"(a.x), "r"(a.y), "r"(a.z), "r"(a.w), "r"(b0), "r"(b1));
}

__global__ void __launch_bounds__(256, 1)
tc_gemm_kernel(const float* __restrict__ X, const float* __restrict__ W) {
    extern __shared__ uint4 sm[];
    uint4* Ahi = sm;
    uint4* Alo = sm + 2048;
    uint4* Bsm = sm + 4096;

    const int tid  = threadIdx.x;
    const int bRow = blockIdx.x * 128;

    // stage W fragments: 8 ks x 16 nt x 32 lanes
#pragma unroll
    for (int i = 0; i < 16; i++) {
        int e = i * 256 + tid;
        int lane = e & 31, rest = e >> 5;
        int nt = rest & 15, ks = rest >> 4;
        int g = lane >> 2, t4 = lane & 3;
        int n = nt * 8 + g, k = ks * 16 + t4 * 2;
        float2 p0 = *(const float2*)&W[n * D + k];
        float2 p1 = *(const float2*)&W[n * D + k + 8];
        uint4 v;
        uint32_t l0, l1;
        bf16_split2(p0.x, p0.y, v.x, l0);
        bf16_split2(p1.x, p1.y, v.y, l1);
        v.z = l0; v.w = l1;
        Bsm[(ks * 16 + nt) * 32 + lane] = v;
    }

    // stage X fragments: 8 ks x 8 mt x 32 lanes
#pragma unroll
    for (int i = 0; i < 8; i++) {
        int e = i * 256 + tid;
        int lane = e & 31, rest = e >> 5;
        int mt = rest & 7, ks = rest >> 3;
        int g = lane >> 2, t4 = lane & 3;
        int r1 = bRow + mt * 16 + g;
        int r2 = r1 + 8;
        int k  = ks * 16 + t4 * 2;
        int r1c = (r1 < NN) ? r1 : NN - 1;
        int r2c = (r2 < NN) ? r2 : NN - 1;
        float2 p0 = *(const float2*)&X[(size_t)r1c * D + k];
        float2 p1 = *(const float2*)&X[(size_t)r2c * D + k];
        float2 p2 = *(const float2*)&X[(size_t)r1c * D + k + 8];
        float2 p3 = *(const float2*)&X[(size_t)r2c * D + k + 8];
        uint4 vh, vl;
        bf16_split2(p0.x, p0.y, vh.x, vl.x);
        bf16_split2(p1.x, p1.y, vh.y, vl.y);
        bf16_split2(p2.x, p2.y, vh.z, vl.z);
        bf16_split2(p3.x, p3.y, vh.w, vl.w);
        int idx = (ks * 8 + mt) * 32 + lane;
        Ahi[idx] = vh;
        Alo[idx] = vl;
    }
    __syncthreads();

    const int warp = tid >> 5, lane = tid & 31;
    const int rg = warp >> 1, cg = warp & 1;
    const int g = lane >> 2, t4 = lane & 3;

    float acc[2][8][4];
#pragma unroll
    for (int m = 0; m < 2; m++)
#pragma unroll
        for (int n = 0; n < 8; n++)
#pragma unroll
            for (int q = 0; q < 4; q++) acc[m][n][q] = 0.f;

#pragma unroll
    for (int ks = 0; ks < 8; ks++) {
        uint4 ah[2], al[2];
#pragma unroll
        for (int m = 0; m < 2; m++) {
            int idx = (ks * 8 + rg * 2 + m) * 32 + lane;
            ah[m] = Ahi[idx];
            al[m] = Alo[idx];
        }
#pragma unroll
        for (int n = 0; n < 8; n++) {
            uint4 b = Bsm[(ks * 16 + cg * 8 + n) * 32 + lane];
#pragma unroll
            for (int m = 0; m < 2; m++) {
                mma16816(acc[m][n], ah[m], b.x, b.y);   // hi*hi
                mma16816(acc[m][n], ah[m], b.z, b.w);   // hi*lo
                mma16816(acc[m][n], al[m], b.x, b.y);   // lo*hi
            }
        }
    }

    // epilogue: write Z as fp16
#pragma unroll
    for (int m = 0; m < 2; m++) {
        int row = bRow + (rg * 2 + m) * 16 + g;
#pragma unroll
        for (int n = 0; n < 8; n++) {
            int col = cg * 64 + n * 8 + t4 * 2;
            if (row < NN)
                *(__half2*)&g_Zh[(size_t)row * D + col] =
                    __floats2half2_rn(acc[m][n][0], acc[m][n][1]);
            if (row + 8 < NN)
                *(__half2*)&g_Zh[(size_t)(row + 8) * D + col] =
                    __floats2half2_rn(acc[m][n][2], acc[m][n][3]);
        }
    }
}

// ---------------------------------------------------------------------------
// Pull-mode aggregation: one warp per node, lane = 4 fp16 cols (8B load),
// fp32 accumulation, single fp32 write. No atomics.
// ---------------------------------------------------------------------------
__device__ __forceinline__ void acc_h4(float4& acc, uint2 v) {
    float2 a = __half22float2(*(const __half2*)&v.x);
    float2 b = __half22float2(*(const __half2*)&v.y);
    acc.x += a.x; acc.y += a.y; acc.z += b.x; acc.w += b.y;
}

__global__ void __launch_bounds__(256)
gather_kernel(const float4* __restrict__ b, float* __restrict__ out) {
    const int node = (blockIdx.x * blockDim.x + threadIdx.x) >> 5;
    if (node >= NN) return;
    const int lane = threadIdx.x & 31;

    const int beg = g_off[node];
    const int end = beg + g_cnt[node];

    float4 acc = b[lane];

    int e = beg;
    for (; e + 4 <= end; e += 4) {
        int s0 = g_esrc[e],     s1 = g_esrc[e + 1];
        int s2 = g_esrc[e + 2], s3 = g_esrc[e + 3];
        uint2 v0 = *(const uint2*)(g_Zh + (size_t)s0 * D + lane * 4);
        uint2 v1 = *(const uint2*)(g_Zh + (size_t)s1 * D + lane * 4);
        uint2 v2 = *(const uint2*)(g_Zh + (size_t)s2 * D + lane * 4);
        uint2 v3 = *(const uint2*)(g_Zh + (size_t)s3 * D + lane * 4);
        acc_h4(acc, v0); acc_h4(acc, v1); acc_h4(acc, v2); acc_h4(acc, v3);
    }
    for (; e < end; e++) {
        int s0 = g_esrc[e];
        uint2 v0 = *(const uint2*)(g_Zh + (size_t)s0 * D + lane * 4);
        acc_h4(acc, v0);
    }

    *(float4*)(out + (size_t)node * D + lane * 4) = acc;
}

// ---------------------------------------------------------------------------
extern "C" void kernel_launch(void* const* d_in, const int* in_sizes, int n_in,
                              void* d_out, int out_size) {
    const float* feature = (const float*)d_in[0];
    const void*  src     = d_in[1];
    const void*  dst     = d_in[2];
    const float* W       = (const float*)d_in[3];
    const float* b       = (const float*)d_in[4];
    float*       out     = (float*)d_out;

    cudaFuncSetAttribute(tc_gemm_kernel,
                         cudaFuncAttributeMaxDynamicSharedMemorySize, TC_SMEM);

    prep_kernel<<<NBLK, SCAN_B>>>((const unsigned int*)src);
    hist_kernel<<<(NE + 255) / 256, 256>>>(dst);
    scan_a_kernel<<<NBLK, SCAN_B>>>();
    scan_c_kernel<<<NBLK, SCAN_B>>>();
    fill_kernel<<<(NE + 255) / 256, 256>>>(src, dst);
    tc_gemm_kernel<<<GEMM_BLOCKS, 256, TC_SMEM>>>(feature, W);
    gather_kernel<<<(NN * 32 + 255) / 256, 256>>>((const float4*)b, out);
}